// round 3
// baseline (speedup 1.0000x reference)
#include <cuda_runtime.h>

// GCN 2-layer, scatter-reassociated + normalization-reassociated + 4-edge
// vectorized edge passes.
//
// t[d]  = dinv[d] * ( dinv[d]*x[d] + sum_e ew * dinv[s]*x[s] )
// out[d]= dinv[d] * ( dinv[d]*hw[d] + sum_e ew * dinv[s]*hw[s] ) + b2
//
// Edge passes do exactly one random gather + one random reduction per edge;
// streaming src/dst/ew reads are vectorized 4 edges/thread (int4/float4) to
// cut L1tex wavefronts 4x and give MLP=4 on the random accesses.

#define NMAX 131072
#define TPB 256

__device__ float  g_dinv[NMAX];   // deg during accumulation, then dinv
__device__ float2 g_xd[NMAX];     // dinv[i] * x[i]          (gather source)
__device__ float2 g_u[NMAX];      // scatter target layer 1  (init = xd)
__device__ float  g_hws[NMAX];    // dinv[i] * hw[i]         (gather source)

// ---- kernel 0: deg init = 1.0 (self-loop weight) ---------------------------
__global__ void k_init(int n) {
    int i = blockIdx.x * blockDim.x + threadIdx.x;
    if (i < n) g_dinv[i] = 1.0f;
}

// ---- kernel 1: deg[dst] += ew  (4 edges/thread) -----------------------------
__global__ void k_deg(const int* __restrict__ dst,
                      const float* __restrict__ ew, int E) {
    int i = blockIdx.x * blockDim.x + threadIdx.x;
    int base = i * 4;
    if (base + 3 < E) {
        int4   d = *(const int4*)(dst + base);
        float4 w = *(const float4*)(ew + base);
        atomicAdd(&g_dinv[d.x], w.x);
        atomicAdd(&g_dinv[d.y], w.y);
        atomicAdd(&g_dinv[d.z], w.z);
        atomicAdd(&g_dinv[d.w], w.w);
    } else {
        for (int e = base; e < E; e++) atomicAdd(&g_dinv[dst[e]], ew[e]);
    }
}

// ---- kernel 2: dinv = rsqrt(deg); xd = dinv*x; u init = xd (self loop) -----
__global__ void k_node1(const float2* __restrict__ x, int n) {
    int i = blockIdx.x * blockDim.x + threadIdx.x;
    if (i >= n) return;
    float d = g_dinv[i];
    float r = (d > 0.0f) ? rsqrtf(d) : 0.0f;
    g_dinv[i] = r;
    float2 xv = x[i];
    float2 xd = make_float2(r * xv.x, r * xv.y);
    g_xd[i] = xd;
    g_u[i]  = xd;   // self-loop term (outer dinv applied later)
}

__device__ __forceinline__ void red_v2(float2* p, float a, float b) {
    asm volatile("red.global.add.v2.f32 [%0], {%1, %2};"
                 :: "l"(p), "f"(a), "f"(b) : "memory");
}

// ---- kernel 3: layer-1 edge scatter: u[d] += ew * xd[s]  (4 edges/thread) ---
__global__ void k_edge1(const int* __restrict__ src,
                        const int* __restrict__ dst,
                        const float* __restrict__ ew, int E) {
    int i = blockIdx.x * blockDim.x + threadIdx.x;
    int base = i * 4;
    if (base + 3 < E) {
        int4   s = *(const int4*)(src + base);
        int4   d = *(const int4*)(dst + base);
        float4 w = *(const float4*)(ew + base);
        float2 x0 = __ldg(&g_xd[s.x]);
        float2 x1 = __ldg(&g_xd[s.y]);
        float2 x2 = __ldg(&g_xd[s.z]);
        float2 x3 = __ldg(&g_xd[s.w]);
        red_v2(&g_u[d.x], w.x * x0.x, w.x * x0.y);
        red_v2(&g_u[d.y], w.y * x1.x, w.y * x1.y);
        red_v2(&g_u[d.z], w.z * x2.x, w.z * x2.y);
        red_v2(&g_u[d.w], w.w * x3.x, w.w * x3.y);
    } else {
        for (int e = base; e < E; e++) {
            float2 xd = __ldg(&g_xd[src[e]]);
            float w = ew[e];
            red_v2(&g_u[dst[e]], w * xd.x, w * xd.y);
        }
    }
}

// ---- kernel 4: t = dinv*u; MLP; hws = dinv*hw; out init = hws ---------------
__global__ void k_node2(const float* __restrict__ W1,
                        const float* __restrict__ b1,
                        const float* __restrict__ W2,
                        float* __restrict__ out, int n) {
    int i = blockIdx.x * blockDim.x + threadIdx.x;
    if (i >= n) return;
    float r = g_dinv[i];
    float2 u = g_u[i];
    float tx = r * u.x;
    float ty = r * u.y;
    float acc = 0.0f;
#pragma unroll
    for (int k = 0; k < 16; k++) {
        float h = fmaf(tx, __ldg(&W1[k]),
                  fmaf(ty, __ldg(&W1[16 + k]), __ldg(&b1[k])));
        h = fmaxf(h, 0.0f);
        acc = fmaf(h, __ldg(&W2[k]), acc);
    }
    float hws = r * acc;
    g_hws[i] = hws;
    out[i]   = hws;   // self-loop init (outer dinv + b2 applied in k_node3)
}

// ---- kernel 5: layer-2 edge scatter: out[d] += ew * hws[s] (4 edges/thread) -
__global__ void k_edge2(const int* __restrict__ src,
                        const int* __restrict__ dst,
                        const float* __restrict__ ew,
                        float* __restrict__ out, int E) {
    int i = blockIdx.x * blockDim.x + threadIdx.x;
    int base = i * 4;
    if (base + 3 < E) {
        int4   s = *(const int4*)(src + base);
        int4   d = *(const int4*)(dst + base);
        float4 w = *(const float4*)(ew + base);
        float h0 = __ldg(&g_hws[s.x]);
        float h1 = __ldg(&g_hws[s.y]);
        float h2 = __ldg(&g_hws[s.z]);
        float h3 = __ldg(&g_hws[s.w]);
        atomicAdd(&out[d.x], w.x * h0);
        atomicAdd(&out[d.y], w.y * h1);
        atomicAdd(&out[d.z], w.z * h2);
        atomicAdd(&out[d.w], w.w * h3);
    } else {
        for (int e = base; e < E; e++)
            atomicAdd(&out[dst[e]], ew[e] * __ldg(&g_hws[src[e]]));
    }
}

// ---- kernel 6: out = dinv*out + b2 ------------------------------------------
__global__ void k_node3(const float* __restrict__ b2,
                        float* __restrict__ out, int n) {
    int i = blockIdx.x * blockDim.x + threadIdx.x;
    if (i >= n) return;
    out[i] = fmaf(g_dinv[i], out[i], __ldg(&b2[0]));
}

extern "C" void kernel_launch(void* const* d_in, const int* in_sizes, int n_in,
                              void* d_out, int out_size) {
    const float* x  = (const float*)d_in[0];   // [N, 2]
    const int*   ei = (const int*)d_in[1];     // [2, E]
    const float* ew = (const float*)d_in[2];   // [E]
    const float* W1 = (const float*)d_in[3];   // [2, 16]
    const float* b1 = (const float*)d_in[4];   // [16]
    const float* W2 = (const float*)d_in[5];   // [16, 1]
    const float* b2 = (const float*)d_in[6];   // [1]
    float* out = (float*)d_out;                // [N, 1]

    int n = in_sizes[0] / 2;
    int E = in_sizes[2];
    const int* src = ei;
    const int* dst = ei + E;

    int nb_n  = (n + TPB - 1) / TPB;
    int E4    = (E + 3) / 4;                   // threads for 4-edge kernels
    int nb_e4 = (E4 + TPB - 1) / TPB;

    k_init <<<nb_n,  TPB>>>(n);
    k_deg  <<<nb_e4, TPB>>>(dst, ew, E);
    k_node1<<<nb_n,  TPB>>>((const float2*)x, n);
    k_edge1<<<nb_e4, TPB>>>(src, dst, ew, E);
    k_node2<<<nb_n,  TPB>>>(W1, b1, W2, out, n);
    k_edge2<<<nb_e4, TPB>>>(src, dst, ew, out, E);
    k_node3<<<nb_n,  TPB>>>(b2, out, n);
}

// round 4
// speedup vs baseline: 1.0495x; 1.0495x over previous
#include <cuda_runtime.h>

// GCN 2-layer, scatter-reassociated + normalization-reassociated.
//
// t[d]  = dinv[d] * ( dinv[d]*x[d] + sum_e ew * dinv[s]*x[s] )
// out[d]= dinv[d] * ( dinv[d]*hw[d] + sum_e ew * dinv[s]*hw[s] ) + b2
//
// Edge passes do exactly one random gather + one random reduction per edge
// (the algorithmic minimum given the deg -> dinv -> layer1 -> layer2 dependency
// chain). Scalar 1-edge/thread proved fastest (R3 post-mortem: vectorizing cut
// warp count and starved the latency-bound random-access pipeline).
//
// R4: Programmatic Dependent Launch on every kernel to hide the ~1-2us launch
// gap between the 7 dependent kernels. Each kernel grid-syncs on its
// predecessor's writes, then immediately triggers prelaunch of its successor.

#define NMAX 131072
#define TPB 256

__device__ float  g_dinv[NMAX];   // deg during accumulation, then dinv
__device__ float2 g_xd[NMAX];     // dinv[i] * x[i]          (gather source)
__device__ float2 g_u[NMAX];      // scatter target layer 1  (init = xd)
__device__ float  g_hws[NMAX];    // dinv[i] * hw[i]         (gather source)

__device__ __forceinline__ void pdl_prologue() {
    cudaGridDependencySynchronize();            // wait for predecessor's writes
    cudaTriggerProgrammaticLaunchCompletion();  // let successor prelaunch early
}

// ---- kernel 0: deg init = 1.0 (self-loop weight) ---------------------------
__global__ void __launch_bounds__(TPB) k_init(int n) {
    pdl_prologue();
    int i = blockIdx.x * blockDim.x + threadIdx.x;
    if (i < n) g_dinv[i] = 1.0f;
}

// ---- kernel 1: deg[dst] += ew ----------------------------------------------
__global__ void __launch_bounds__(TPB) k_deg(const int* __restrict__ dst,
                                             const float* __restrict__ ew, int E) {
    pdl_prologue();
    int e = blockIdx.x * blockDim.x + threadIdx.x;
    if (e < E) atomicAdd(&g_dinv[dst[e]], ew[e]);
}

// ---- kernel 2: dinv = rsqrt(deg); xd = dinv*x; u init = xd (self loop) -----
__global__ void __launch_bounds__(TPB) k_node1(const float2* __restrict__ x, int n) {
    pdl_prologue();
    int i = blockIdx.x * blockDim.x + threadIdx.x;
    if (i >= n) return;
    float d = g_dinv[i];
    float r = (d > 0.0f) ? rsqrtf(d) : 0.0f;
    g_dinv[i] = r;
    float2 xv = x[i];
    float2 xd = make_float2(r * xv.x, r * xv.y);
    g_xd[i] = xd;
    g_u[i]  = xd;   // self-loop term (outer dinv applied later)
}

// ---- kernel 3: layer-1 edge scatter: u[d] += ew * xd[s] ---------------------
__global__ void __launch_bounds__(TPB) k_edge1(const int* __restrict__ src,
                                               const int* __restrict__ dst,
                                               const float* __restrict__ ew, int E) {
    pdl_prologue();
    int e = blockIdx.x * blockDim.x + threadIdx.x;
    if (e >= E) return;
    int s = src[e];
    int d = dst[e];
    float w = ew[e];
    float2 xd = __ldg(&g_xd[s]);
    float a = w * xd.x;
    float b = w * xd.y;
    asm volatile("red.global.add.v2.f32 [%0], {%1, %2};"
                 :: "l"(&g_u[d]), "f"(a), "f"(b) : "memory");
}

// ---- kernel 4: t = dinv*u; MLP; hws = dinv*hw; out init = hws ---------------
__global__ void __launch_bounds__(TPB) k_node2(const float* __restrict__ W1,
                                               const float* __restrict__ b1,
                                               const float* __restrict__ W2,
                                               float* __restrict__ out, int n) {
    pdl_prologue();
    int i = blockIdx.x * blockDim.x + threadIdx.x;
    if (i >= n) return;
    float r = g_dinv[i];
    float2 u = g_u[i];
    float tx = r * u.x;
    float ty = r * u.y;
    float acc = 0.0f;
#pragma unroll
    for (int k = 0; k < 16; k++) {
        float h = fmaf(tx, __ldg(&W1[k]),
                  fmaf(ty, __ldg(&W1[16 + k]), __ldg(&b1[k])));
        h = fmaxf(h, 0.0f);
        acc = fmaf(h, __ldg(&W2[k]), acc);
    }
    float hws = r * acc;
    g_hws[i] = hws;
    out[i]   = hws;   // self-loop init (outer dinv + b2 applied in k_node3)
}

// ---- kernel 5: layer-2 edge scatter: out[d] += ew * hws[s] ------------------
__global__ void __launch_bounds__(TPB) k_edge2(const int* __restrict__ src,
                                               const int* __restrict__ dst,
                                               const float* __restrict__ ew,
                                               float* __restrict__ out, int E) {
    pdl_prologue();
    int e = blockIdx.x * blockDim.x + threadIdx.x;
    if (e >= E) return;
    int s = src[e];
    int d = dst[e];
    atomicAdd(&out[d], ew[e] * __ldg(&g_hws[s]));
}

// ---- kernel 6: out = dinv*out + b2 ------------------------------------------
__global__ void __launch_bounds__(TPB) k_node3(const float* __restrict__ b2,
                                               float* __restrict__ out, int n) {
    pdl_prologue();
    int i = blockIdx.x * blockDim.x + threadIdx.x;
    if (i >= n) return;
    out[i] = fmaf(g_dinv[i], out[i], __ldg(&b2[0]));
}

// ---- host: launch all kernels with programmatic stream serialization --------
template <typename F, typename... Args>
static void launch_pdl(F kernel, int nblocks, Args... args) {
    cudaLaunchConfig_t cfg = {};
    cfg.gridDim  = dim3((unsigned)nblocks, 1, 1);
    cfg.blockDim = dim3(TPB, 1, 1);
    cfg.dynamicSmemBytes = 0;
    cfg.stream = 0;  // legacy default stream (what the harness captures)
    cudaLaunchAttribute attr[1];
    attr[0].id = cudaLaunchAttributeProgrammaticStreamSerialization;
    attr[0].val.programmaticStreamSerializationAllowed = 1;
    cfg.attrs = attr;
    cfg.numAttrs = 1;
    cudaLaunchKernelEx(&cfg, kernel, args...);
}

extern "C" void kernel_launch(void* const* d_in, const int* in_sizes, int n_in,
                              void* d_out, int out_size) {
    const float* x  = (const float*)d_in[0];   // [N, 2]
    const int*   ei = (const int*)d_in[1];     // [2, E]
    const float* ew = (const float*)d_in[2];   // [E]
    const float* W1 = (const float*)d_in[3];   // [2, 16]
    const float* b1 = (const float*)d_in[4];   // [16]
    const float* W2 = (const float*)d_in[5];   // [16, 1]
    const float* b2 = (const float*)d_in[6];   // [1]
    float* out = (float*)d_out;                // [N, 1]

    int n = in_sizes[0] / 2;
    int E = in_sizes[2];
    const int* src = ei;
    const int* dst = ei + E;

    int nb_n = (n + TPB - 1) / TPB;
    int nb_e = (E + TPB - 1) / TPB;

    launch_pdl(k_init,  nb_n, n);
    launch_pdl(k_deg,   nb_e, dst, ew, E);
    launch_pdl(k_node1, nb_n, (const float2*)x, n);
    launch_pdl(k_edge1, nb_e, src, dst, ew, E);
    launch_pdl(k_node2, nb_n, W1, b1, W2, out, n);
    launch_pdl(k_edge2, nb_e, src, dst, ew, out, E);
    launch_pdl(k_node3, nb_n, b2, out, n);
}